// round 7
// baseline (speedup 1.0000x reference)
#include <cuda_runtime.h>

// SlowNorm: per-irrep L2 norms.
// irreps: (256,1) (256,3) (128,5) (64,7)  -> DIM=2112 in, OUT=704 out per row.
// Input offsets (floats): d1 [0,256), d3 [256,1024), d5 [1024,1664), d7 [1664,2112).
// Output offsets: [0,256) |x| ; [256,512) d=3 ; [512,640) d=5 ; [640,704) d=7.
//
// R5 design scaled to 3 rows/CTA: 25.3KB smem still allows 8 CTAs/SM (full
// 2048-thread occupancy) while stage MLP rises to 6 front-batched LDG.128
// per thread. d=1 block bypasses smem (|x| stored directly during staging).

#define DIM      2112
#define OUT_DIM  704
#define THREADS  256
#define ROWS     3
#define F4_ROW   (DIM / 4)               // 528
#define F4_TOTAL (ROWS * F4_ROW)         // 1584 = 6*256 + 48
#define CHUNKS_PER_ROW 112               // q in [64,176)
#define CHUNKS_TOTAL   (ROWS * CHUNKS_PER_ROW)  // 336 = 256 + 80

__device__ __forceinline__ float4 ldcs4(const float4* p) {
    float4 v;
    asm volatile("ld.global.cs.v4.f32 {%0,%1,%2,%3}, [%4];\n"
                 : "=f"(v.x), "=f"(v.y), "=f"(v.z), "=f"(v.w) : "l"(p));
    return v;
}
__device__ __forceinline__ void stcs4(float4* p, float4 v) {
    asm volatile("st.global.cs.v4.f32 [%0], {%1,%2,%3,%4};\n"
                 :: "l"(p), "f"(v.x), "f"(v.y), "f"(v.z), "f"(v.w));
}

__device__ __forceinline__ void compute_chunk(
    const float* __restrict__ s, float4* __restrict__ dst4, int c)
{
    const int r = c / CHUNKS_PER_ROW;
    const int q = 64 + (c - r * CHUNKS_PER_ROW);
    const float* __restrict__ b = s + r * DIM;
    float a[4];
    if (q < 128) {                           // d=3
        const int p = 256 + (4 * q - 256) * 3;
        #pragma unroll
        for (int k = 0; k < 4; k++) {
            const float* e = b + p + 3 * k;
            float acc = e[0] * e[0];
            acc = fmaf(e[1], e[1], acc);
            acc = fmaf(e[2], e[2], acc);
            a[k] = sqrtf(acc);
        }
    } else if (q < 160) {                    // d=5
        const int p = 1024 + (4 * q - 512) * 5;
        #pragma unroll
        for (int k = 0; k < 4; k++) {
            const float* e = b + p + 5 * k;
            float acc = e[0] * e[0];
            #pragma unroll
            for (int j = 1; j < 5; j++) acc = fmaf(e[j], e[j], acc);
            a[k] = sqrtf(acc);
        }
    } else {                                 // d=7
        const int p = 1664 + (4 * q - 640) * 7;
        #pragma unroll
        for (int k = 0; k < 4; k++) {
            const float* e = b + p + 7 * k;
            float acc = e[0] * e[0];
            #pragma unroll
            for (int j = 1; j < 7; j++) acc = fmaf(e[j], e[j], acc);
            a[k] = sqrtf(acc);
        }
    }
    float4 v; v.x = a[0]; v.y = a[1]; v.z = a[2]; v.w = a[3];
    stcs4(dst4 + r * (OUT_DIM / 4) + q, v);
}

__global__ __launch_bounds__(THREADS) void slownorm_kernel(
    const float* __restrict__ in, float* __restrict__ out)
{
    __shared__ float s[ROWS * DIM];      // 25344 B -> 8 CTAs/SM

    const int tid = threadIdx.x;
    const long long row0 = (long long)blockIdx.x * ROWS;
    const float4* __restrict__ src =
        reinterpret_cast<const float4*>(in + row0 * DIM);
    float4* __restrict__ dst4 =
        reinterpret_cast<float4*>(out + row0 * OUT_DIM);
    float4* s4 = reinterpret_cast<float4*>(s);

    // ---- Stage: 1584 float4 = 6 full strides + 48-thread tail ----
    float4 x[6];
    #pragma unroll
    for (int k = 0; k < 6; k++)
        x[k] = ldcs4(src + tid + k * THREADS);
    float4 xt;
    if (tid < F4_TOTAL - 6 * THREADS)    // 48 float4 -> row 2, w 480..527
        xt = ldcs4(src + 6 * THREADS + tid);

    #pragma unroll
    for (int k = 0; k < 6; k++) {
        const int i = tid + k * THREADS;
        const int r = i / F4_ROW;
        const int w = i - r * F4_ROW;
        if (w < 64) {
            // d=1: |x| straight to output (output chunk q == w).
            float4 v;
            v.x = fabsf(x[k].x); v.y = fabsf(x[k].y);
            v.z = fabsf(x[k].z); v.w = fabsf(x[k].w);
            stcs4(dst4 + r * (OUT_DIM / 4) + w, v);
        } else {
            s4[i] = x[k];
        }
    }
    if (tid < F4_TOTAL - 6 * THREADS)
        s4[6 * THREADS + tid] = xt;      // tail all w>=64
    __syncthreads();

    // ---- Compute: 336 chunks = full pass + 80-thread pass ----
    compute_chunk(s, dst4, tid);
    if (tid < CHUNKS_TOTAL - THREADS)
        compute_chunk(s, dst4, THREADS + tid);
}

extern "C" void kernel_launch(void* const* d_in, const int* in_sizes, int n_in,
                              void* d_out, int out_size)
{
    const float* features = (const float*)d_in[0];
    float* out = (float*)d_out;
    const int batch = in_sizes[0] / DIM;        // 65536; 65536/3 -> need ceil
    const int grid = (batch + ROWS - 1) / ROWS; // 21846; last CTA handles 1 row
    // batch = 65536 = 3*21845 + 1: guard overflow rows inside? 65536 % 3 = 1.
    slownorm_kernel<<<batch / ROWS, THREADS>>>(features, out);
    // Handle the 65536 % ROWS = 1 remainder row with a tiny 1-row launch
    // reusing the same kernel shape via pointer offset (ROWS=3 kernel reads
    // 3 rows, so instead launch a dedicated small grid is needed). Simpler:
    // the remainder is processed by one extra CTA below via offset trick is
    // NOT safe (would read past end). Use the scalar-safe path:
    {
        const long long done = (long long)(batch / ROWS) * ROWS;  // 65535
        const int rem = batch - (int)done;                        // 1
        if (rem > 0) {
            // one CTA, 1-row variant: reuse kernel by staging from the last
            // full ROWS-row window ending at batch (overlap is harmless:
            // recomputing rows is deterministic and writes same values).
            const long long start = batch - ROWS;                 // 65533
            slownorm_kernel<<<1, THREADS>>>(features + start * DIM,
                                            out + start * OUT_DIM);
        }
    }
    (void)grid;
}

// round 8
// speedup vs baseline: 1.0411x; 1.0411x over previous
#include <cuda_runtime.h>

// SlowNorm: per-irrep L2 norms.
// irreps: (256,1) (256,3) (128,5) (64,7)  -> DIM=2112 in, OUT=704 out per row.
// Input offsets (floats): d1 [0,256), d3 [256,1024), d5 [1024,1664), d7 [1664,2112).
// Output offsets: [0,256) |x| ; [256,512) d=3 ; [512,640) d=5 ; [640,704) d=7.
//
// R5 shape (2 rows/CTA, 17KB smem, high occupancy, d=1 bypass during staging)
// + vectorized compute phase: every output chunk's smem span is 16B-aligned
// (bases 12q-512 / 20q-1536 / 28q-2816 floats, all multiples of 4), so chunk
// reads use LDS.128 (3/5/7 loads) instead of 12/20/28 scalar LDS.

#define DIM      2112
#define OUT_DIM  704
#define THREADS  256
#define ROWS     2
#define F4_ROW   (DIM / 4)               // 528
#define F4_TOTAL (ROWS * F4_ROW)         // 1056 = 4*256 + 32
#define CHUNKS_PER_ROW 112               // q in [64,176)
#define CHUNKS_TOTAL   (ROWS * CHUNKS_PER_ROW)  // 224 (< THREADS)

__device__ __forceinline__ float4 ldcs4(const float4* p) {
    float4 v;
    asm volatile("ld.global.cs.v4.f32 {%0,%1,%2,%3}, [%4];\n"
                 : "=f"(v.x), "=f"(v.y), "=f"(v.z), "=f"(v.w) : "l"(p));
    return v;
}
__device__ __forceinline__ void stcs4(float4* p, float4 v) {
    asm volatile("st.global.cs.v4.f32 [%0], {%1,%2,%3,%4};\n"
                 :: "l"(p), "f"(v.x), "f"(v.y), "f"(v.z), "f"(v.w));
}

__global__ __launch_bounds__(THREADS) void slownorm_kernel(
    const float* __restrict__ in, float* __restrict__ out)
{
    __shared__ float s[ROWS * DIM];      // 16896 B

    const int tid = threadIdx.x;
    const long long row0 = (long long)blockIdx.x * ROWS;
    const float4* __restrict__ src =
        reinterpret_cast<const float4*>(in + row0 * DIM);
    float4* __restrict__ dst4 =
        reinterpret_cast<float4*>(out + row0 * OUT_DIM);
    float4* s4 = reinterpret_cast<float4*>(s);

    // ---- Stage: 1056 float4 = 4 full strides + 32-thread tail ----
    float4 x[4];
    #pragma unroll
    for (int k = 0; k < 4; k++)
        x[k] = ldcs4(src + tid + k * THREADS);
    float4 xt;
    if (tid < F4_TOTAL - 4 * THREADS)    // tail: 32 float4 (row 1, w 496..527)
        xt = ldcs4(src + 4 * THREADS + tid);

    #pragma unroll
    for (int k = 0; k < 4; k++) {
        const int i = tid + k * THREADS;
        const int r = i / F4_ROW;
        const int w = i - r * F4_ROW;
        if (w < 64) {
            // d=1: |x| straight to output (output chunk q == w).
            float4 v;
            v.x = fabsf(x[k].x); v.y = fabsf(x[k].y);
            v.z = fabsf(x[k].z); v.w = fabsf(x[k].w);
            stcs4(dst4 + r * (OUT_DIM / 4) + w, v);
        } else {
            s4[i] = x[k];
        }
    }
    if (tid < F4_TOTAL - 4 * THREADS)
        s4[4 * THREADS + tid] = xt;      // tail is all w>=64 (row 1)
    __syncthreads();

    // ---- Compute: 224 chunks, one per thread, LDS.128 reads ----
    if (tid < CHUNKS_TOTAL) {
        const int r = tid / CHUNKS_PER_ROW;
        const int q = 64 + (tid - r * CHUNKS_PER_ROW);
        const float4* __restrict__ b4 =
            reinterpret_cast<const float4*>(s + r * DIM);
        float a[4];
        if (q < 128) {                           // d=3: 3 float4 at 3q-128
            float4 t[3];
            const float4* p = b4 + (3 * q - 128);
            #pragma unroll
            for (int k = 0; k < 3; k++) t[k] = p[k];
            const float* f = reinterpret_cast<const float*>(t);
            #pragma unroll
            for (int k = 0; k < 4; k++) {
                const float* e = f + 3 * k;
                float acc = e[0] * e[0];
                acc = fmaf(e[1], e[1], acc);
                acc = fmaf(e[2], e[2], acc);
                a[k] = sqrtf(acc);
            }
        } else if (q < 160) {                    // d=5: 5 float4 at 5q-384
            float4 t[5];
            const float4* p = b4 + (5 * q - 384);
            #pragma unroll
            for (int k = 0; k < 5; k++) t[k] = p[k];
            const float* f = reinterpret_cast<const float*>(t);
            #pragma unroll
            for (int k = 0; k < 4; k++) {
                const float* e = f + 5 * k;
                float acc = e[0] * e[0];
                #pragma unroll
                for (int j = 1; j < 5; j++) acc = fmaf(e[j], e[j], acc);
                a[k] = sqrtf(acc);
            }
        } else {                                 // d=7: 7 float4 at 7q-704
            float4 t[7];
            const float4* p = b4 + (7 * q - 704);
            #pragma unroll
            for (int k = 0; k < 7; k++) t[k] = p[k];
            const float* f = reinterpret_cast<const float*>(t);
            #pragma unroll
            for (int k = 0; k < 4; k++) {
                const float* e = f + 7 * k;
                float acc = e[0] * e[0];
                #pragma unroll
                for (int j = 1; j < 7; j++) acc = fmaf(e[j], e[j], acc);
                a[k] = sqrtf(acc);
            }
        }
        float4 v; v.x = a[0]; v.y = a[1]; v.z = a[2]; v.w = a[3];
        stcs4(dst4 + r * (OUT_DIM / 4) + q, v);
    }
}

extern "C" void kernel_launch(void* const* d_in, const int* in_sizes, int n_in,
                              void* d_out, int out_size)
{
    const float* features = (const float*)d_in[0];
    float* out = (float*)d_out;
    const int batch = in_sizes[0] / DIM;        // 65536 (even)
    slownorm_kernel<<<batch / ROWS, THREADS>>>(features, out);
}

// round 9
// speedup vs baseline: 1.0415x; 1.0003x over previous
#include <cuda_runtime.h>

// SlowNorm: per-irrep L2 norms.
// irreps: (256,1) (256,3) (128,5) (64,7)  -> DIM=2112 in, OUT=704 out per row.
// Input offsets (floats): d1 [0,256), d3 [256,1024), d5 [1024,1664), d7 [1664,2112).
// Output offsets: [0,256) |x| ; [256,512) d=3 ; [512,640) d=5 ; [640,704) d=7.
//
// 2 rows/CTA, 17KB smem (8 CTAs/SM), d=1 bypass during staging, LDS.128
// compute with STREAMING accumulation: each loaded float4 is folded into the
// 4 output accumulators immediately (indices (4k+j)/d are compile-time
// constants after unroll), keeping live regs ~10 instead of 28.

#define DIM      2112
#define OUT_DIM  704
#define THREADS  256
#define ROWS     2
#define F4_ROW   (DIM / 4)               // 528
#define F4_TOTAL (ROWS * F4_ROW)         // 1056 = 4*256 + 32
#define CHUNKS_PER_ROW 112               // q in [64,176)
#define CHUNKS_TOTAL   (ROWS * CHUNKS_PER_ROW)  // 224 (< THREADS)

__device__ __forceinline__ float4 ldcs4(const float4* p) {
    float4 v;
    asm volatile("ld.global.cs.v4.f32 {%0,%1,%2,%3}, [%4];\n"
                 : "=f"(v.x), "=f"(v.y), "=f"(v.z), "=f"(v.w) : "l"(p));
    return v;
}
__device__ __forceinline__ void stcs4(float4* p, float4 v) {
    asm volatile("st.global.cs.v4.f32 [%0], {%1,%2,%3,%4};\n"
                 :: "l"(p), "f"(v.x), "f"(v.y), "f"(v.z), "f"(v.w));
}

// Stream NF4 float4s from smem, accumulating x^2 into a[(4k+j)/D].
template <int D, int NF4>
__device__ __forceinline__ void norm_chunk(const float4* __restrict__ p,
                                           float a[4])
{
    a[0] = 0.f; a[1] = 0.f; a[2] = 0.f; a[3] = 0.f;
    #pragma unroll
    for (int k = 0; k < NF4; k++) {
        const float4 t = p[k];
        a[(4 * k + 0) / D] = fmaf(t.x, t.x, a[(4 * k + 0) / D]);
        a[(4 * k + 1) / D] = fmaf(t.y, t.y, a[(4 * k + 1) / D]);
        a[(4 * k + 2) / D] = fmaf(t.z, t.z, a[(4 * k + 2) / D]);
        a[(4 * k + 3) / D] = fmaf(t.w, t.w, a[(4 * k + 3) / D]);
    }
    #pragma unroll
    for (int k = 0; k < 4; k++) a[k] = sqrtf(a[k]);
}

__global__ __launch_bounds__(THREADS) void slownorm_kernel(
    const float* __restrict__ in, float* __restrict__ out)
{
    __shared__ float s[ROWS * DIM];      // 16896 B

    const int tid = threadIdx.x;
    const long long row0 = (long long)blockIdx.x * ROWS;
    const float4* __restrict__ src =
        reinterpret_cast<const float4*>(in + row0 * DIM);
    float4* __restrict__ dst4 =
        reinterpret_cast<float4*>(out + row0 * OUT_DIM);
    float4* s4 = reinterpret_cast<float4*>(s);

    // ---- Stage: 1056 float4 = 4 full strides + 32-thread tail ----
    float4 x[4];
    #pragma unroll
    for (int k = 0; k < 4; k++)
        x[k] = ldcs4(src + tid + k * THREADS);
    float4 xt;
    if (tid < F4_TOTAL - 4 * THREADS)    // tail: 32 float4 (row 1, w 496..527)
        xt = ldcs4(src + 4 * THREADS + tid);

    #pragma unroll
    for (int k = 0; k < 4; k++) {
        const int i = tid + k * THREADS;
        const int r = i / F4_ROW;
        const int w = i - r * F4_ROW;
        if (w < 64) {
            // d=1: |x| straight to output (output chunk q == w).
            float4 v;
            v.x = fabsf(x[k].x); v.y = fabsf(x[k].y);
            v.z = fabsf(x[k].z); v.w = fabsf(x[k].w);
            stcs4(dst4 + r * (OUT_DIM / 4) + w, v);
        } else {
            s4[i] = x[k];
        }
    }
    if (tid < F4_TOTAL - 4 * THREADS)
        s4[4 * THREADS + tid] = xt;      // tail is all w>=64 (row 1)
    __syncthreads();

    // ---- Compute: 224 chunks, one per thread, streaming LDS.128 ----
    if (tid < CHUNKS_TOTAL) {
        const int r = tid / CHUNKS_PER_ROW;
        const int q = 64 + (tid - r * CHUNKS_PER_ROW);
        const float4* __restrict__ b4 =
            reinterpret_cast<const float4*>(s + r * DIM);
        float a[4];
        if (q < 128) {                           // d=3: 3 float4 at 3q-128
            norm_chunk<3, 3>(b4 + (3 * q - 128), a);
        } else if (q < 160) {                    // d=5: 5 float4 at 5q-384
            norm_chunk<5, 5>(b4 + (5 * q - 384), a);
        } else {                                 // d=7: 7 float4 at 7q-704
            norm_chunk<7, 7>(b4 + (7 * q - 704), a);
        }
        float4 v; v.x = a[0]; v.y = a[1]; v.z = a[2]; v.w = a[3];
        stcs4(dst4 + r * (OUT_DIM / 4) + q, v);
    }
}

extern "C" void kernel_launch(void* const* d_in, const int* in_sizes, int n_in,
                              void* d_out, int out_size)
{
    const float* features = (const float*)d_in[0];
    float* out = (float*)d_out;
    const int batch = in_sizes[0] / DIM;        // 65536 (even)
    slownorm_kernel<<<batch / ROWS, THREADS>>>(features, out);
}